// round 1
// baseline (speedup 1.0000x reference)
#include <cuda_runtime.h>
#include <math.h>

#define S_LEN   128
#define BATCH   1024
#define D0      300
#define D1      74
#define D2      35
#define HID     40
#define EMB     256
#define MM      3
#define RED_DIM 115            // 2*HID + D2
#define KTOT    377            // RED_DIM + 2*MM + EMB
#define NROWS   (S_LEN*BATCH)

// -------------------- device scratch (no allocations allowed) --------------------
__device__ float g_reduced[(size_t)NROWS * RED_DIM];   // [S*B][115]
__device__ float g_h[2][BATCH * EMB];                  // ping-pong hidden state
__device__ float g_c[BATCH * EMB];                     // cell state (in-place safe)

__device__ __forceinline__ float sigm(float x) { return 1.f / (1.f + expf(-x)); }

// -------------------- init: zero recurrent state --------------------
__global__ void init_kernel() {
    int i = blockIdx.x * blockDim.x + threadIdx.x;
    if (i < BATCH * EMB) {
        g_h[0][i] = 0.f;
        g_h[1][i] = 0.f;
        g_c[i]    = 0.f;
    }
}

// -------------------- phase 1: reduced = [x0@W0.T+b0 | x1@W1.T+b1 | x2] --------------------
// blockDim = 320, 32 rows per block. Dynamic smem: W0 (40*300) + W1 padded (40*76).
__global__ void phase1_kernel(const float* __restrict__ x0, const float* __restrict__ x1,
                              const float* __restrict__ x2,
                              const float* __restrict__ W0, const float* __restrict__ b0p,
                              const float* __restrict__ W1, const float* __restrict__ b1p) {
    extern __shared__ float sm[];
    float* sW0 = sm;                 // 40*300 floats
    float* sW1 = sm + 40 * 300;      // 40*76 floats (cols 74,75 zero)
    const int tid = threadIdx.x;

    for (int i = tid; i < 40 * 300; i += 320) sW0[i] = W0[i];
    for (int i = tid; i < 40 * 76; i += 320) {
        int r = i / 76, c = i % 76;
        sW1[i] = (c < D1) ? W1[r * D1 + c] : 0.f;
    }
    __syncthreads();

    const int r0 = blockIdx.x * 32;
    const int o  = tid % 40;          // output column within HID
    const int rb = (tid / 40) * 4;    // 8 groups * 4 rows = 32 rows

    // ---- part A: x0 @ W0.T + b0 -> cols [0,40) ----
    {
        const float bv = b0p[o];
        float acc[4] = {bv, bv, bv, bv};
        const float4* wv = (const float4*)(sW0 + o * D0);
        const float4* xr[4];
#pragma unroll
        for (int j = 0; j < 4; j++)
            xr[j] = (const float4*)(x0 + (size_t)(r0 + rb + j) * D0);
#pragma unroll 5
        for (int k4 = 0; k4 < 75; k4++) {
            float4 w = wv[k4];
#pragma unroll
            for (int j = 0; j < 4; j++) {
                float4 a = __ldg(&xr[j][k4]);
                acc[j] += w.x * a.x + w.y * a.y + w.z * a.z + w.w * a.w;
            }
        }
#pragma unroll
        for (int j = 0; j < 4; j++)
            g_reduced[(size_t)(r0 + rb + j) * RED_DIM + o] = acc[j];
    }

    // ---- part B: x1 @ W1.T + b1 -> cols [40,80) ----
    {
        const float bv = b1p[o];
        float acc[4] = {bv, bv, bv, bv};
        const float2* wv = (const float2*)(sW1 + o * 76);
        const float2* xr[4];
#pragma unroll
        for (int j = 0; j < 4; j++)
            xr[j] = (const float2*)(x1 + (size_t)(r0 + rb + j) * D1);
#pragma unroll 4
        for (int k2 = 0; k2 < 37; k2++) {
            float2 w = wv[k2];
#pragma unroll
            for (int j = 0; j < 4; j++) {
                float2 a = __ldg(&xr[j][k2]);
                acc[j] += w.x * a.x + w.y * a.y;
            }
        }
#pragma unroll
        for (int j = 0; j < 4; j++)
            g_reduced[(size_t)(r0 + rb + j) * RED_DIM + HID + o] = acc[j];
    }

    // ---- part C: copy x2 -> cols [80,115) ----
    for (int i = tid; i < 32 * D2; i += 320) {
        int r = i / D2, c = i % D2;
        g_reduced[(size_t)(r0 + r) * RED_DIM + 2 * HID + c] =
            x2[(size_t)(r0 + r) * D2 + c];
    }
}

// -------------------- fused per-step kernel --------------------
// grid (16, 8), block 256.
//   prologue: decoder + gumbel for step t-1 (from g_h[t&1]), fills sPrev, writes outputs
//   mainloop: gates GEMM 64b x (32e x 4 gates), K=377 in 12 chunks of 32
//   epilogue: LSTM cell -> g_c in-place, g_h[(t+1)&1]
// tail call (t == S_LEN, tail=1, grid (16,1)): prologue only (final decoder).
__global__ void __launch_bounds__(256) step_kernel(
    int t, int tail,
    const float* __restrict__ W_ih, const float* __restrict__ W_hh,
    const float* __restrict__ b_ih, const float* __restrict__ b_hh,
    const float* __restrict__ W_dec, const float* __restrict__ b_dec,
    const float* __restrict__ gum, float* __restrict__ out) {

    __shared__ __align__(16) float sA[64 * 36];
    __shared__ __align__(16) float sB[128 * 36];
    __shared__ float sPrev[64 * 6];

    const int tid  = threadIdx.x;
    const int lane = tid & 31;
    const int warp = tid >> 5;          // 0..7
    const int bb0  = blockIdx.x * 64;
    const int e0   = blockIdx.y * 32;
    const int hb   = t & 1;
    const float* __restrict__ hprev = g_h[hb];

    // ---------------- prologue: decoder for step t-1 ----------------
    if (t == 0) {
        for (int i = tid; i < 64 * 6; i += 256) sPrev[i] = 0.f;
    } else {
        const int tprev = t - 1;
        const bool wr = (blockIdx.y == 0);
        for (int r2 = 0; r2 < 8; r2++) {
            const int b = bb0 + warp * 8 + r2;
            float hv[8];
#pragma unroll
            for (int i = 0; i < 8; i++) hv[i] = hprev[b * EMB + lane + 32 * i];
            float lg[6];
#pragma unroll
            for (int mo = 0; mo < 6; mo++) {
                float p = 0.f;
#pragma unroll
                for (int i = 0; i < 8; i++)
                    p += hv[i] * __ldg(&W_dec[mo * EMB + lane + 32 * i]);
                p += __shfl_xor_sync(0xffffffffu, p, 16);
                p += __shfl_xor_sync(0xffffffffu, p, 8);
                p += __shfl_xor_sync(0xffffffffu, p, 4);
                p += __shfl_xor_sync(0xffffffffu, p, 2);
                p += __shfl_xor_sync(0xffffffffu, p, 1);
                p += __ldg(&b_dec[mo]);
                lg[mo] = p;
                if (lane == mo) sPrev[(warp * 8 + r2) * 6 + mo] = p;
            }
            if (wr && lane == 0) {
#pragma unroll
                for (int m = 0; m < MM; m++) {
                    size_t gbase = ((size_t)tprev * (MM * BATCH) + m * BATCH + b) * 2;
                    float u0 = gum[gbase], u1 = gum[gbase + 1];
                    float gg0 = -logf(-logf(u0));
                    float gg1 = -logf(-logf(u1));
                    float l0 = lg[2 * m], l1 = lg[2 * m + 1];
                    out[((size_t)tprev * MM + m) * BATCH + b] =
                        (l1 + gg1 > l0 + gg0) ? 1.f : 0.f;
                    size_t lbase = (size_t)S_LEN * MM * BATCH +
                                   (((size_t)tprev * MM + m) * BATCH + b) * 2;
                    out[lbase]     = l0;
                    out[lbase + 1] = l1;
                }
            }
        }
    }
    __syncthreads();
    if (tail) return;

    // ---------------- gates GEMM ----------------
    const int e_idx = lane;      // e within tile
    const int bg    = warp;      // 8 b-rows per thread group
    const int e     = e0 + e_idx;

    float acc0[8], acc1[8], acc2[8], acc3[8];
    {
        const float bia0 = b_ih[0 * EMB + e] + b_hh[0 * EMB + e];
        const float bia1 = b_ih[1 * EMB + e] + b_hh[1 * EMB + e];
        const float bia2 = b_ih[2 * EMB + e] + b_hh[2 * EMB + e];
        const float bia3 = b_ih[3 * EMB + e] + b_hh[3 * EMB + e];
#pragma unroll
        for (int j = 0; j < 8; j++) {
            acc0[j] = bia0; acc1[j] = bia1; acc2[j] = bia2; acc3[j] = bia3;
        }
    }

    const float* __restrict__ red_t = g_reduced + (size_t)t * BATCH * RED_DIM;

    for (int c = 0; c < 12; c++) {
        const int kbase = c * 32;
        // A tile: 64 rows x 32 k  (xcat gather)
        for (int i = tid; i < 2048; i += 256) {
            int r = i >> 5, kk = i & 31;
            int kg = kbase + kk;
            int b = bb0 + r;
            float v;
            if (kg < RED_DIM)            v = red_t[(size_t)b * RED_DIM + kg];
            else if (kg < RED_DIM + 6)   v = sPrev[r * 6 + (kg - RED_DIM)];
            else if (kg < KTOT)          v = hprev[b * EMB + (kg - RED_DIM - 6)];
            else                         v = 0.f;
            sA[r * 36 + kk] = v;
        }
        // B tile: 128 rows (4 gates x 32 e) x 32 k
        for (int i = tid; i < 4096; i += 256) {
            int j = i >> 5, kk = i & 31;
            int kg = kbase + kk;
            int grow = (j >> 5) * EMB + e0 + (j & 31);
            float v;
            if (kg < RED_DIM + 6)  v = W_ih[grow * (RED_DIM + 6) + kg];
            else if (kg < KTOT)    v = W_hh[grow * EMB + (kg - RED_DIM - 6)];
            else                   v = 0.f;
            sB[j * 36 + kk] = v;
        }
        __syncthreads();

#pragma unroll
        for (int k4 = 0; k4 < 8; k4++) {
            float4 w0 = *(const float4*)(sB + (0  + e_idx) * 36 + k4 * 4);
            float4 w1 = *(const float4*)(sB + (32 + e_idx) * 36 + k4 * 4);
            float4 w2 = *(const float4*)(sB + (64 + e_idx) * 36 + k4 * 4);
            float4 w3 = *(const float4*)(sB + (96 + e_idx) * 36 + k4 * 4);
#pragma unroll
            for (int j = 0; j < 8; j++) {
                float4 a = *(const float4*)(sA + (bg * 8 + j) * 36 + k4 * 4);
                acc0[j] += w0.x * a.x + w0.y * a.y + w0.z * a.z + w0.w * a.w;
                acc1[j] += w1.x * a.x + w1.y * a.y + w1.z * a.z + w1.w * a.w;
                acc2[j] += w2.x * a.x + w2.y * a.y + w2.z * a.z + w2.w * a.w;
                acc3[j] += w3.x * a.x + w3.y * a.y + w3.z * a.z + w3.w * a.w;
            }
        }
        __syncthreads();
    }

    // ---------------- LSTM cell epilogue ----------------
    const int nb = (t + 1) & 1;
#pragma unroll
    for (int j = 0; j < 8; j++) {
        const int b   = bb0 + bg * 8 + j;
        const int idx = b * EMB + e;
        float iv = sigm(acc0[j]);
        float fv = sigm(acc1[j]);
        float gv = tanhf(acc2[j]);
        float ov = sigm(acc3[j]);
        float cn = fv * g_c[idx] + iv * gv;
        g_c[idx] = cn;
        g_h[nb][idx] = ov * tanhf(cn);
    }
}

// -------------------- launch --------------------
extern "C" void kernel_launch(void* const* d_in, const int* in_sizes, int n_in,
                              void* d_out, int out_size) {
    const float* x0    = (const float*)d_in[0];
    const float* x1    = (const float*)d_in[1];
    const float* x2    = (const float*)d_in[2];
    // d_in[3] = x_lens (unused)
    const float* gum   = (const float*)d_in[4];
    const float* W0    = (const float*)d_in[5];
    const float* b0    = (const float*)d_in[6];
    const float* W1    = (const float*)d_in[7];
    const float* b1    = (const float*)d_in[8];
    const float* W_ih  = (const float*)d_in[9];
    const float* W_hh  = (const float*)d_in[10];
    const float* b_ih  = (const float*)d_in[11];
    const float* b_hh  = (const float*)d_in[12];
    const float* W_dec = (const float*)d_in[13];
    const float* b_dec = (const float*)d_in[14];
    float* out = (float*)d_out;

    init_kernel<<<(BATCH * EMB + 255) / 256, 256>>>();

    size_t smem1 = (size_t)(40 * 300 + 40 * 76) * sizeof(float);   // 60160 B
    cudaFuncSetAttribute(phase1_kernel,
                         cudaFuncAttributeMaxDynamicSharedMemorySize, (int)smem1);
    phase1_kernel<<<NROWS / 32, 320, smem1>>>(x0, x1, x2, W0, b0, W1, b1);

    for (int t = 0; t < S_LEN; t++)
        step_kernel<<<dim3(16, 8), 256>>>(t, 0, W_ih, W_hh, b_ih, b_hh,
                                          W_dec, b_dec, gum, out);
    // final decoder for h_127
    step_kernel<<<dim3(16, 1), 256>>>(S_LEN, 1, W_ih, W_hh, b_ih, b_hh,
                                      W_dec, b_dec, gum, out);
}

// round 2
// speedup vs baseline: 1.8241x; 1.8241x over previous
#include <cuda_runtime.h>
#include <math.h>

#define S_LEN   128
#define BATCH   1024
#define D0      300
#define D1      74
#define D2      35
#define HID     40
#define EMB     256
#define MM      3
#define RED_DIM 115            // 2*HID + D2
#define LSTM_IN 121            // RED_DIM + 2*MM
#define KTOT    377            // LSTM_IN + EMB
#define K4TOT   96             // ceil(377/4) padded to chunk multiple (12 chunks * 8)
#define NROWS   (S_LEN*BATCH)
#define NBLK    128

// -------------------- device scratch (no allocations allowed) --------------------
__device__ float g_reduced[(size_t)NROWS * RED_DIM];   // [S*B][115]
__device__ float g_h[2][BATCH * EMB];                  // ping-pong hidden state
__device__ float g_c[BATCH * EMB];                     // cell state (block-exclusive cells)
__device__ unsigned g_count;                           // global barrier counter

__device__ __forceinline__ float sigm(float x) { return 1.f / (1.f + expf(-x)); }

// -------------------- init: zero recurrent state + barrier --------------------
__global__ void init_kernel() {
    int i = blockIdx.x * blockDim.x + threadIdx.x;
    if (i == 0) g_count = 0u;
    if (i < BATCH * EMB) {
        g_h[0][i] = 0.f;
        g_h[1][i] = 0.f;
        g_c[i]    = 0.f;
    }
}

// -------------------- phase 1: reduced = [x0@W0.T+b0 | x1@W1.T+b1 | x2] --------------------
__global__ void phase1_kernel(const float* __restrict__ x0, const float* __restrict__ x1,
                              const float* __restrict__ x2,
                              const float* __restrict__ W0, const float* __restrict__ b0p,
                              const float* __restrict__ W1, const float* __restrict__ b1p) {
    extern __shared__ float sm[];
    float* sW0 = sm;                 // 40*300 floats
    float* sW1 = sm + 40 * 300;      // 40*76 floats (cols 74,75 zero)
    const int tid = threadIdx.x;

    for (int i = tid; i < 40 * 300; i += 320) sW0[i] = W0[i];
    for (int i = tid; i < 40 * 76; i += 320) {
        int r = i / 76, c = i % 76;
        sW1[i] = (c < D1) ? W1[r * D1 + c] : 0.f;
    }
    __syncthreads();

    const int r0 = blockIdx.x * 32;
    const int o  = tid % 40;          // output column within HID
    const int rb = (tid / 40) * 4;    // 8 groups * 4 rows = 32 rows

    // ---- part A: x0 @ W0.T + b0 -> cols [0,40) ----
    {
        const float bv = b0p[o];
        float acc[4] = {bv, bv, bv, bv};
        const float4* wv = (const float4*)(sW0 + o * D0);
        const float4* xr[4];
#pragma unroll
        for (int j = 0; j < 4; j++)
            xr[j] = (const float4*)(x0 + (size_t)(r0 + rb + j) * D0);
#pragma unroll 5
        for (int k4 = 0; k4 < 75; k4++) {
            float4 w = wv[k4];
#pragma unroll
            for (int j = 0; j < 4; j++) {
                float4 a = __ldg(&xr[j][k4]);
                acc[j] += w.x * a.x + w.y * a.y + w.z * a.z + w.w * a.w;
            }
        }
#pragma unroll
        for (int j = 0; j < 4; j++)
            g_reduced[(size_t)(r0 + rb + j) * RED_DIM + o] = acc[j];
    }

    // ---- part B: x1 @ W1.T + b1 -> cols [40,80) ----
    {
        const float bv = b1p[o];
        float acc[4] = {bv, bv, bv, bv};
        const float2* wv = (const float2*)(sW1 + o * 76);
        const float2* xr[4];
#pragma unroll
        for (int j = 0; j < 4; j++)
            xr[j] = (const float2*)(x1 + (size_t)(r0 + rb + j) * D1);
#pragma unroll 4
        for (int k2 = 0; k2 < 37; k2++) {
            float2 w = wv[k2];
#pragma unroll
            for (int j = 0; j < 4; j++) {
                float2 a = __ldg(&xr[j][k2]);
                acc[j] += w.x * a.x + w.y * a.y;
            }
        }
#pragma unroll
        for (int j = 0; j < 4; j++)
            g_reduced[(size_t)(r0 + rb + j) * RED_DIM + HID + o] = acc[j];
    }

    // ---- part C: copy x2 -> cols [80,115) ----
    for (int i = tid; i < 32 * D2; i += 320) {
        int r = i / D2, c = i % D2;
        g_reduced[(size_t)(r0 + r) * RED_DIM + 2 * HID + c] =
            x2[(size_t)(r0 + r) * D2 + c];
    }
}

// -------------------- persistent recurrent kernel --------------------
// grid = 128 blocks (all co-resident, 1/SM), block = 256 threads.
// Block (bt, et) owns batch rows [bt*64, bt*64+64) and gate-cols [et*32, et*32+32) of all 4 gates.
// Weight slab (128 rows x 384 k, k4-major float4) lives in smem for all 128 steps.
// Per step: decoder prologue (prev logits + gumbel outputs), 12 K-chunks of GEMM,
// LSTM cell epilogue, software global barrier.
__global__ void __launch_bounds__(256, 1) persist_kernel(
    const float* __restrict__ W_ih, const float* __restrict__ W_hh,
    const float* __restrict__ b_ih, const float* __restrict__ b_hh,
    const float* __restrict__ W_dec, const float* __restrict__ b_dec,
    const float* __restrict__ gum, float* __restrict__ out) {

    extern __shared__ __align__(16) float4 smp[];
    float4* sB    = smp;                       // [96*128] float4 : 192 KB, resident weights
    float4* sA    = smp + K4TOT * 128;         // [8*64]  float4 : 8 KB, per-chunk activations
    float*  sPrev = (float*)(sA + 8 * 64);     // [64*6]  floats : prev logits

    const int tid  = threadIdx.x;
    const int lane = tid & 31;
    const int warp = tid >> 5;                 // 0..7
    const int bt   = blockIdx.x & 15;
    const int et   = blockIdx.x >> 4;          // 0..7
    const int bb0  = bt * 64;
    const int e0   = et * 32;
    const int e    = e0 + lane;

    // ---- one-time: load weight slab into smem, k4-major ----
    // sB[k4*128 + j], j = gate*32 + (col - e0); value = float4 of k = 4*k4 .. 4*k4+3
    for (int i = tid; i < K4TOT * 128; i += 256) {
        int k4 = i >> 7, j = i & 127;
        int grow = (j >> 5) * EMB + e0 + (j & 31);
        int kg0 = k4 * 4;
        float4 v; float* vp = (float*)&v;
#pragma unroll
        for (int q = 0; q < 4; q++) {
            int kk = kg0 + q;
            float w;
            if (kk < LSTM_IN)    w = W_ih[grow * LSTM_IN + kk];
            else if (kk < KTOT)  w = W_hh[grow * EMB + (kk - LSTM_IN)];
            else                 w = 0.f;
            vp[q] = w;
        }
        sB[i] = v;
    }
    float bia[4];
#pragma unroll
    for (int g = 0; g < 4; g++) bia[g] = b_ih[g * EMB + e] + b_hh[g * EMB + e];

    for (int t = 0; t <= S_LEN; t++) {
        const float* __restrict__ hprev = g_h[t & 1];

        // ---------------- prologue: decoder + gumbel for step t-1 ----------------
        if (t == 0) {
            for (int i = tid; i < 64 * 6; i += 256) sPrev[i] = 0.f;
        } else {
            const int tprev = t - 1;
            const bool wr = (et == 0);
            for (int r2 = 0; r2 < 8; r2++) {
                const int b = bb0 + warp * 8 + r2;
                float hv[8];
#pragma unroll
                for (int i = 0; i < 8; i++) hv[i] = __ldcg(&hprev[b * EMB + lane + 32 * i]);
                float lg[6];
#pragma unroll
                for (int mo = 0; mo < 6; mo++) {
                    float p = 0.f;
#pragma unroll
                    for (int i = 0; i < 8; i++)
                        p += hv[i] * __ldg(&W_dec[mo * EMB + lane + 32 * i]);
                    p += __shfl_xor_sync(0xffffffffu, p, 16);
                    p += __shfl_xor_sync(0xffffffffu, p, 8);
                    p += __shfl_xor_sync(0xffffffffu, p, 4);
                    p += __shfl_xor_sync(0xffffffffu, p, 2);
                    p += __shfl_xor_sync(0xffffffffu, p, 1);
                    p += __ldg(&b_dec[mo]);
                    lg[mo] = p;
                    if (lane == mo) sPrev[(warp * 8 + r2) * 6 + mo] = p;
                }
                if (wr && lane < MM) {
                    const int m = lane;
                    size_t gbase = ((size_t)tprev * (MM * BATCH) + m * BATCH + b) * 2;
                    float u0 = gum[gbase], u1 = gum[gbase + 1];
                    float gg0 = -logf(-logf(u0));
                    float gg1 = -logf(-logf(u1));
                    float l0 = lg[2 * m], l1 = lg[2 * m + 1];
                    out[((size_t)tprev * MM + m) * BATCH + b] =
                        (l1 + gg1 > l0 + gg0) ? 1.f : 0.f;
                    size_t lbase = (size_t)S_LEN * MM * BATCH +
                                   (((size_t)tprev * MM + m) * BATCH + b) * 2;
                    out[lbase]     = l0;
                    out[lbase + 1] = l1;
                }
            }
        }
        if (t == S_LEN) break;     // final decoder only
        __syncthreads();           // sPrev ready; prior sA use done

        const float* __restrict__ red_t = g_reduced + (size_t)t * BATCH * RED_DIM;

        float acc0[8], acc1[8], acc2[8], acc3[8];
#pragma unroll
        for (int j = 0; j < 8; j++) {
            acc0[j] = bia[0]; acc1[j] = bia[1]; acc2[j] = bia[2]; acc3[j] = bia[3];
        }

        for (int c = 0; c < 12; c++) {
            // ---- fill sA (8 k4 x 64 rows), k4-major float4 ----
#pragma unroll
            for (int i0 = 0; i0 < 2; i0++) {
                int i = tid + i0 * 256;
                int k4l = i >> 6, r = i & 63;
                int b = bb0 + r;
                int kg0 = c * 32 + k4l * 4;
                float4 v; float* vp = (float*)&v;
                if (kg0 + 3 < RED_DIM) {
#pragma unroll
                    for (int q = 0; q < 4; q++)
                        vp[q] = __ldg(&red_t[(size_t)b * RED_DIM + kg0 + q]);
                } else if (kg0 >= LSTM_IN && kg0 + 3 < KTOT) {
#pragma unroll
                    for (int q = 0; q < 4; q++)
                        vp[q] = __ldcg(&hprev[b * EMB + (kg0 - LSTM_IN) + q]);
                } else {
#pragma unroll
                    for (int q = 0; q < 4; q++) {
                        int kg = kg0 + q;
                        float x;
                        if (kg < RED_DIM)       x = __ldg(&red_t[(size_t)b * RED_DIM + kg]);
                        else if (kg < LSTM_IN)  x = sPrev[r * 6 + (kg - RED_DIM)];
                        else if (kg < KTOT)     x = __ldcg(&hprev[b * EMB + (kg - LSTM_IN)]);
                        else                    x = 0.f;
                        vp[q] = x;
                    }
                }
                sA[k4l * 64 + r] = v;
            }
            __syncthreads();

            // ---- FFMA mainloop: conflict-free w loads, broadcast a loads ----
#pragma unroll
            for (int k4 = 0; k4 < 8; k4++) {
                const float4* bRow = sB + (c * 8 + k4) * 128;
                const float4 w0 = bRow[lane];
                const float4 w1 = bRow[32 + lane];
                const float4 w2 = bRow[64 + lane];
                const float4 w3 = bRow[96 + lane];
#pragma unroll
                for (int j = 0; j < 8; j++) {
                    const float4 a = sA[k4 * 64 + warp * 8 + j];
                    acc0[j] += w0.x * a.x + w0.y * a.y + w0.z * a.z + w0.w * a.w;
                    acc1[j] += w1.x * a.x + w1.y * a.y + w1.z * a.z + w1.w * a.w;
                    acc2[j] += w2.x * a.x + w2.y * a.y + w2.z * a.z + w2.w * a.w;
                    acc3[j] += w3.x * a.x + w3.y * a.y + w3.z * a.z + w3.w * a.w;
                }
            }
            __syncthreads();
        }

        // ---------------- LSTM cell epilogue ----------------
        const int nb = (t + 1) & 1;
#pragma unroll
        for (int j = 0; j < 8; j++) {
            const int b   = bb0 + warp * 8 + j;
            const int idx = b * EMB + e;
            float iv = sigm(acc0[j]);
            float fv = sigm(acc1[j]);
            float gv = tanhf(acc2[j]);
            float ov = sigm(acc3[j]);
            float cn = fv * g_c[idx] + iv * gv;
            g_c[idx] = cn;
            g_h[nb][idx] = ov * tanhf(cn);
        }

        // ---------------- global barrier ----------------
        __syncthreads();
        if (tid == 0) {
            __threadfence();
            atomicAdd(&g_count, 1u);
            const unsigned tgt = (unsigned)(t + 1) * NBLK;
            while (*(volatile unsigned*)&g_count < tgt) __nanosleep(64);
        }
        __syncthreads();
    }
}

// -------------------- launch --------------------
extern "C" void kernel_launch(void* const* d_in, const int* in_sizes, int n_in,
                              void* d_out, int out_size) {
    const float* x0    = (const float*)d_in[0];
    const float* x1    = (const float*)d_in[1];
    const float* x2    = (const float*)d_in[2];
    // d_in[3] = x_lens (unused)
    const float* gum   = (const float*)d_in[4];
    const float* W0    = (const float*)d_in[5];
    const float* b0    = (const float*)d_in[6];
    const float* W1    = (const float*)d_in[7];
    const float* b1    = (const float*)d_in[8];
    const float* W_ih  = (const float*)d_in[9];
    const float* W_hh  = (const float*)d_in[10];
    const float* b_ih  = (const float*)d_in[11];
    const float* b_hh  = (const float*)d_in[12];
    const float* W_dec = (const float*)d_in[13];
    const float* b_dec = (const float*)d_in[14];
    float* out = (float*)d_out;

    init_kernel<<<(BATCH * EMB + 255) / 256, 256>>>();

    size_t smem1 = (size_t)(40 * 300 + 40 * 76) * sizeof(float);   // 60160 B
    cudaFuncSetAttribute(phase1_kernel,
                         cudaFuncAttributeMaxDynamicSharedMemorySize, (int)smem1);
    phase1_kernel<<<NROWS / 32, 320, smem1>>>(x0, x1, x2, W0, b0, W1, b1);

    size_t smemP = (size_t)(K4TOT * 128 + 8 * 64) * sizeof(float4) +
                   (size_t)(64 * 6) * sizeof(float);               // 206,336 B
    cudaFuncSetAttribute(persist_kernel,
                         cudaFuncAttributeMaxDynamicSharedMemorySize, (int)smemP);
    persist_kernel<<<NBLK, 256, smemP>>>(W_ih, W_hh, b_ih, b_hh,
                                         W_dec, b_dec, gum, out);
}

// round 3
// speedup vs baseline: 2.2244x; 1.2194x over previous
#include <cuda_runtime.h>
#include <math.h>

typedef unsigned long long ull;

#define S_LEN   128
#define BATCH   1024
#define D0      300
#define D1      74
#define D2      35
#define HID     40
#define EMB     256
#define MM      3
#define RED_DIM 115            // 2*HID + D2
#define LSTM_IN 121            // RED_DIM + 2*MM
#define KTOT    377            // LSTM_IN + EMB
#define KPAD    384            // 12 chunks * 32
#define NROWS   (S_LEN*BATCH)
#define NBLK    128
#define GRP     8              // blocks per bt-group barrier
#define A_STR   33             // ull stride per A row (32 k + 1 pad)

// -------------------- device scratch --------------------
__device__ float g_reduced[(size_t)NROWS * RED_DIM];   // [S*B][115]
__device__ float g_h[2][BATCH * EMB];                  // ping-pong hidden state
__device__ unsigned g_counts[16];                      // per-bt-group barrier counters

__device__ __forceinline__ float sigm(float x) { return 1.f / (1.f + expf(-x)); }

__device__ __forceinline__ ull pack2(float lo, float hi) {
    ull r;
    asm("mov.b64 %0, {%1, %2};" : "=l"(r) : "f"(lo), "f"(hi));
    return r;
}
__device__ __forceinline__ void unpack2(ull v, float& lo, float& hi) {
    asm("mov.b64 {%0, %1}, %2;" : "=f"(lo), "=f"(hi) : "l"(v));
}
#define FMA2(acc, a, w) asm("fma.rn.f32x2 %0, %1, %2, %0;" : "+l"(acc) : "l"(a), "l"(w))

// -------------------- init --------------------
__global__ void init_kernel() {
    int i = blockIdx.x * blockDim.x + threadIdx.x;
    if (i < 16) g_counts[i] = 0u;
    if (i < BATCH * EMB) {
        g_h[0][i] = 0.f;
        g_h[1][i] = 0.f;
    }
}

// -------------------- phase 1: reduced = [x0@W0.T+b0 | x1@W1.T+b1 | x2] --------------------
__global__ void phase1_kernel(const float* __restrict__ x0, const float* __restrict__ x1,
                              const float* __restrict__ x2,
                              const float* __restrict__ W0, const float* __restrict__ b0p,
                              const float* __restrict__ W1, const float* __restrict__ b1p) {
    extern __shared__ float sm[];
    float* sW0 = sm;                 // 40*300
    float* sW1 = sm + 40 * 300;      // 40*76 (cols 74,75 zero)
    const int tid = threadIdx.x;

    for (int i = tid; i < 40 * 300; i += 320) sW0[i] = W0[i];
    for (int i = tid; i < 40 * 76; i += 320) {
        int r = i / 76, c = i % 76;
        sW1[i] = (c < D1) ? W1[r * D1 + c] : 0.f;
    }
    __syncthreads();

    const int r0 = blockIdx.x * 32;
    const int o  = tid % 40;
    const int rb = (tid / 40) * 4;

    {
        const float bv = b0p[o];
        float acc[4] = {bv, bv, bv, bv};
        const float4* wv = (const float4*)(sW0 + o * D0);
        const float4* xr[4];
#pragma unroll
        for (int j = 0; j < 4; j++)
            xr[j] = (const float4*)(x0 + (size_t)(r0 + rb + j) * D0);
#pragma unroll 5
        for (int k4 = 0; k4 < 75; k4++) {
            float4 w = wv[k4];
#pragma unroll
            for (int j = 0; j < 4; j++) {
                float4 a = __ldg(&xr[j][k4]);
                acc[j] += w.x * a.x + w.y * a.y + w.z * a.z + w.w * a.w;
            }
        }
#pragma unroll
        for (int j = 0; j < 4; j++)
            g_reduced[(size_t)(r0 + rb + j) * RED_DIM + o] = acc[j];
    }
    {
        const float bv = b1p[o];
        float acc[4] = {bv, bv, bv, bv};
        const float2* wv = (const float2*)(sW1 + o * 76);
        const float2* xr[4];
#pragma unroll
        for (int j = 0; j < 4; j++)
            xr[j] = (const float2*)(x1 + (size_t)(r0 + rb + j) * D1);
#pragma unroll 4
        for (int k2 = 0; k2 < 37; k2++) {
            float2 w = wv[k2];
#pragma unroll
            for (int j = 0; j < 4; j++) {
                float2 a = __ldg(&xr[j][k2]);
                acc[j] += w.x * a.x + w.y * a.y;
            }
        }
#pragma unroll
        for (int j = 0; j < 4; j++)
            g_reduced[(size_t)(r0 + rb + j) * RED_DIM + HID + o] = acc[j];
    }
    for (int i = tid; i < 32 * D2; i += 320) {
        int r = i / D2, c = i % D2;
        g_reduced[(size_t)(r0 + r) * RED_DIM + 2 * HID + c] =
            x2[(size_t)(r0 + r) * D2 + c];
    }
}

// -------------------- persistent recurrent kernel --------------------
// grid = 128 blocks, 1/SM, block = 256 threads. Block (bt,et): batch rows
// [bt*64,+64), gate-cols [et*32,+32) of all 4 gates. Weights resident in smem
// as gate-pair-packed ull: (W_i,W_f) and (W_g,W_o). GEMM inner loop uses
// fma.rn.f32x2 (2 fp32 MACs/instr). sA double-buffered with register prefetch.
// Cell state lives in registers. Per-bt-group (8-block) barrier between steps.
__global__ void __launch_bounds__(256, 1) persist_kernel(
    const float* __restrict__ W_ih, const float* __restrict__ W_hh,
    const float* __restrict__ b_ih, const float* __restrict__ b_hh,
    const float* __restrict__ W_dec, const float* __restrict__ b_dec,
    const float* __restrict__ gum, float* __restrict__ out) {

    extern __shared__ __align__(16) ull smd[];
    ull*   sB2   = smd;                        // [KPAD*64]      = 24576 ull (192 KB)
    ull*   sA0   = smd + KPAD * 64;            // [64*A_STR]     = 2112 ull
    ull*   sA1   = sA0 + 64 * A_STR;           // [64*A_STR]
    float* sPrev = (float*)(sA1 + 64 * A_STR); // [64*6]

    const int tid  = threadIdx.x;
    const int lane = tid & 31;
    const int warp = tid >> 5;                 // 0..7
    const int bt   = blockIdx.x & 15;
    const int et   = blockIdx.x >> 4;          // 0..7
    const int bb0  = bt * 64;
    const int e0   = et * 32;
    const int e    = e0 + lane;

    // ---- one-time: weight slab, gate-pair packed ----
    // sB2[k*64 + pair*32 + col] = ( W[2*pair][e0+col][k], W[2*pair+1][e0+col][k] )
    for (int i = tid; i < KPAD * 64; i += 256) {
        int k = i >> 6, idx = i & 63;
        int pair = idx >> 5, col = idx & 31;
        int grow0 = (2 * pair) * EMB + e0 + col;
        int grow1 = grow0 + EMB;
        float w0, w1;
        if (k < LSTM_IN)      { w0 = W_ih[grow0 * LSTM_IN + k];        w1 = W_ih[grow1 * LSTM_IN + k]; }
        else if (k < KTOT)    { w0 = W_hh[grow0 * EMB + k - LSTM_IN];  w1 = W_hh[grow1 * EMB + k - LSTM_IN]; }
        else                  { w0 = 0.f; w1 = 0.f; }
        sB2[i] = pack2(w0, w1);
    }
    ull biaIF = pack2(b_ih[0 * EMB + e] + b_hh[0 * EMB + e],
                      b_ih[1 * EMB + e] + b_hh[1 * EMB + e]);
    ull biaGO = pack2(b_ih[2 * EMB + e] + b_hh[2 * EMB + e],
                      b_ih[3 * EMB + e] + b_hh[3 * EMB + e]);

    // register-resident cell state: c for rows warp*8+j, col e
    float creg[8];
#pragma unroll
    for (int j = 0; j < 8; j++) creg[j] = 0.f;

    // prefetch mapping: this thread owns row pr, k-offsets pk..pk+7 of each chunk
    const int pr = tid >> 2;          // 0..63
    const int pk = (tid & 3) * 8;     // 0,8,16,24
    const int pb = bb0 + pr;

    volatile unsigned* bar = &g_counts[bt];

    for (int t = 0; t <= S_LEN; t++) {
        const float* __restrict__ hprev = g_h[t & 1];
        const float* __restrict__ red_t = g_reduced + (size_t)t * BATCH * RED_DIM;

        float pf[8];
        // ---- prefetch chunk 0 (k 0..31 < RED_DIM: pure red_t, no h/sPrev dep) ----
        if (t < S_LEN) {
#pragma unroll
            for (int q = 0; q < 8; q++)
                pf[q] = __ldg(&red_t[(size_t)pb * RED_DIM + pk + q]);
        }

        // ---------------- prologue: decoder + gumbel for step t-1 ----------------
        if (t == 0) {
            for (int i = tid; i < 64 * 6; i += 256) sPrev[i] = 0.f;
        } else {
            const int tprev = t - 1;
            const bool wr = (et == 0);
            for (int r2 = 0; r2 < 8; r2++) {
                const int b = bb0 + warp * 8 + r2;
                float hv[8];
#pragma unroll
                for (int i = 0; i < 8; i++) hv[i] = __ldcg(&hprev[b * EMB + lane + 32 * i]);
                float lg[6];
#pragma unroll
                for (int mo = 0; mo < 6; mo++) {
                    float p = 0.f;
#pragma unroll
                    for (int i = 0; i < 8; i++)
                        p += hv[i] * __ldg(&W_dec[mo * EMB + lane + 32 * i]);
                    p += __shfl_xor_sync(0xffffffffu, p, 16);
                    p += __shfl_xor_sync(0xffffffffu, p, 8);
                    p += __shfl_xor_sync(0xffffffffu, p, 4);
                    p += __shfl_xor_sync(0xffffffffu, p, 2);
                    p += __shfl_xor_sync(0xffffffffu, p, 1);
                    p += __ldg(&b_dec[mo]);
                    lg[mo] = p;
                    if (lane == mo) sPrev[(warp * 8 + r2) * 6 + mo] = p;
                }
                if (wr && lane < MM) {
                    const int m = lane;
                    size_t gbase = ((size_t)tprev * (MM * BATCH) + m * BATCH + b) * 2;
                    float u0 = gum[gbase], u1 = gum[gbase + 1];
                    float gg0 = -logf(-logf(u0));
                    float gg1 = -logf(-logf(u1));
                    float l0 = lg[2 * m], l1 = lg[2 * m + 1];
                    out[((size_t)tprev * MM + m) * BATCH + b] =
                        (l1 + gg1 > l0 + gg0) ? 1.f : 0.f;
                    size_t lbase = (size_t)S_LEN * MM * BATCH +
                                   (((size_t)tprev * MM + m) * BATCH + b) * 2;
                    out[lbase]     = l0;
                    out[lbase + 1] = l1;
                }
            }
        }
        if (t == S_LEN) break;
        __syncthreads();                       // sPrev ready

        // ---- stage chunk 0, prefetch chunk 1 ----
        {
            ull* dst = sA0 + pr * A_STR + pk;
#pragma unroll
            for (int q = 0; q < 8; q++) dst[q] = pack2(pf[q], pf[q]);
#pragma unroll
            for (int q = 0; q < 8; q++) {
                int kg = 32 + pk + q;          // chunk 1: 32..63 < RED_DIM
                pf[q] = __ldg(&red_t[(size_t)pb * RED_DIM + kg]);
            }
        }
        __syncthreads();                       // sA0 ready

        ull accIF[8], accGO[8];
#pragma unroll
        for (int j = 0; j < 8; j++) { accIF[j] = biaIF; accGO[j] = biaGO; }

        for (int c = 0; c < 12; c++) {
            const ull* bk = sB2 + (size_t)c * 32 * 64;
            const ull* ak = ((c & 1) ? sA1 : sA0) + warp * 8 * A_STR;
#pragma unroll 8
            for (int k = 0; k < 32; k++) {
                ull wIF = bk[k * 64 + lane];
                ull wGO = bk[k * 64 + 32 + lane];
#pragma unroll
                for (int j = 0; j < 8; j++) {
                    ull a = ak[j * A_STR + k];
                    FMA2(accIF[j], a, wIF);
                    FMA2(accGO[j], a, wGO);
                }
            }
            __syncthreads();                   // all done reading buf[(c+1)&1]
            if (c + 1 < 12) {
                ull* dst = ((c & 1) ? sA0 : sA1) + pr * A_STR + pk;
#pragma unroll
                for (int q = 0; q < 8; q++) dst[q] = pack2(pf[q], pf[q]);
                if (c + 2 < 12) {
                    const int kb = (c + 2) * 32 + pk;
#pragma unroll
                    for (int q = 0; q < 8; q++) {
                        int kg = kb + q;
                        float v;
                        if (kg < RED_DIM)        v = __ldg(&red_t[(size_t)pb * RED_DIM + kg]);
                        else if (kg < LSTM_IN)   v = sPrev[pr * 6 + (kg - RED_DIM)];
                        else if (kg < KTOT)      v = __ldcg(&hprev[pb * EMB + (kg - LSTM_IN)]);
                        else                     v = 0.f;
                        pf[q] = v;
                    }
                }
            }
            __syncthreads();                   // next buffer ready
        }

        // ---------------- LSTM cell epilogue ----------------
        const int nb = (t + 1) & 1;
#pragma unroll
        for (int j = 0; j < 8; j++) {
            const int b = bb0 + warp * 8 + j;
            float iv_raw, fv_raw, gv_raw, ov_raw;
            unpack2(accIF[j], iv_raw, fv_raw);
            unpack2(accGO[j], gv_raw, ov_raw);
            float iv = sigm(iv_raw);
            float fv = sigm(fv_raw);
            float gv = tanhf(gv_raw);
            float ov = sigm(ov_raw);
            float cn = fv * creg[j] + iv * gv;
            creg[j] = cn;
            g_h[nb][b * EMB + e] = ov * tanhf(cn);
        }

        // ---------------- per-bt-group barrier (8 blocks) ----------------
        __syncthreads();
        if (tid == 0) {
            __threadfence();
            atomicAdd((unsigned*)bar, 1u);
            const unsigned tgt = (unsigned)(t + 1) * GRP;
            while (*bar < tgt) __nanosleep(32);
        }
        __syncthreads();
    }
}

// -------------------- launch --------------------
extern "C" void kernel_launch(void* const* d_in, const int* in_sizes, int n_in,
                              void* d_out, int out_size) {
    const float* x0    = (const float*)d_in[0];
    const float* x1    = (const float*)d_in[1];
    const float* x2    = (const float*)d_in[2];
    // d_in[3] = x_lens (unused)
    const float* gum   = (const float*)d_in[4];
    const float* W0    = (const float*)d_in[5];
    const float* b0    = (const float*)d_in[6];
    const float* W1    = (const float*)d_in[7];
    const float* b1    = (const float*)d_in[8];
    const float* W_ih  = (const float*)d_in[9];
    const float* W_hh  = (const float*)d_in[10];
    const float* b_ih  = (const float*)d_in[11];
    const float* b_hh  = (const float*)d_in[12];
    const float* W_dec = (const float*)d_in[13];
    const float* b_dec = (const float*)d_in[14];
    float* out = (float*)d_out;

    init_kernel<<<(BATCH * EMB + 255) / 256, 256>>>();

    size_t smem1 = (size_t)(40 * 300 + 40 * 76) * sizeof(float);   // 60160 B
    cudaFuncSetAttribute(phase1_kernel,
                         cudaFuncAttributeMaxDynamicSharedMemorySize, (int)smem1);
    phase1_kernel<<<NROWS / 32, 320, smem1>>>(x0, x1, x2, W0, b0, W1, b1);

    size_t smemP = (size_t)(KPAD * 64 + 2 * 64 * A_STR) * sizeof(ull) +
                   (size_t)(64 * 6) * sizeof(float);               // 231,936 B
    cudaFuncSetAttribute(persist_kernel,
                         cudaFuncAttributeMaxDynamicSharedMemorySize, (int)smemP);
    persist_kernel<<<NBLK, 256, smemP>>>(W_ih, W_hh, b_ih, b_hh,
                                         W_dec, b_dec, gum, out);
}